// round 1
// baseline (speedup 1.0000x reference)
#include <cuda_runtime.h>
#include <math.h>

#define BB 32
#define SQ 200
#define SMEMLEN 1024
#define DMODEL 1024
#define NH 16
#define HD 64
#define DFF 4096
#define NT (BB*SQ)        // 6400 target tokens
#define MTOK (BB*SMEMLEN) // 32768 memory tokens
#define EPS 1e-5f

// ---------------- scratch (device globals; no allocation allowed) ----------------
__device__ float g_h[NT*DMODEL];
__device__ float g_roped[NT*DMODEL];
__device__ float g_q[NT*DMODEL];
__device__ float g_k[MTOK*DMODEL];
__device__ float g_v[MTOK*DMODEL];
__device__ float g_attn[NT*DMODEL];
__device__ float g_x[NT*DMODEL];
__device__ float g_ffh[NT*DFF];

// ---------------- LayerNorm: one block per token, D=1024 ----------------
__global__ __launch_bounds__(256) void ln_kernel(const float* __restrict__ x,
                                                 const float* __restrict__ g,
                                                 const float* __restrict__ b,
                                                 float* __restrict__ out) {
    __shared__ float rs[8], rss[8];
    int t = blockIdx.x;
    int tid = threadIdx.x;
    const float4* xr = (const float4*)(x + (size_t)t * DMODEL);
    float4 v = xr[tid];
    float s  = v.x + v.y + v.z + v.w;
    float ss = v.x*v.x + v.y*v.y + v.z*v.z + v.w*v.w;
    #pragma unroll
    for (int o = 16; o; o >>= 1) {
        s  += __shfl_xor_sync(0xffffffffu, s, o);
        ss += __shfl_xor_sync(0xffffffffu, ss, o);
    }
    int lane = tid & 31, wid = tid >> 5;
    if (lane == 0) { rs[wid] = s; rss[wid] = ss; }
    __syncthreads();
    float ts = 0.f, tss = 0.f;
    #pragma unroll
    for (int w = 0; w < 8; w++) { ts += rs[w]; tss += rss[w]; }
    float mu  = ts * (1.0f / DMODEL);
    float var = tss * (1.0f / DMODEL) - mu * mu;
    float r   = rsqrtf(var + EPS);
    float4 gv = ((const float4*)g)[tid];
    float4 bv = ((const float4*)b)[tid];
    float4 o;
    o.x = (v.x - mu) * r * gv.x + bv.x;
    o.y = (v.y - mu) * r * gv.y + bv.y;
    o.z = (v.z - mu) * r * gv.z + bv.z;
    o.w = (v.w - mu) * r * gv.w + bv.w;
    ((float4*)(out + (size_t)t * DMODEL))[tid] = o;
}

// ---------------- RoPE: one thread per (token, pair) ----------------
__global__ void rope_kernel(const float* __restrict__ in, float* __restrict__ out) {
    int idx = blockIdx.x * blockDim.x + threadIdx.x;   // pair index
    if (idx >= NT * (DMODEL / 2)) return;
    int t = idx / (DMODEL / 2);
    int p = idx - t * (DMODEL / 2);
    int i = p & 31;              // pair index within head (0..31)
    int s = t % SQ;              // position
    // freq = 10000^(-(2i)/64)
    float freq = __expf(-9.210340371976184f * (2.0f * i) * (1.0f / 64.0f));
    float ang = (float)s * freq;
    float sn, cs;
    sincosf(ang, &sn, &cs);
    const float2 xv = ((const float2*)in)[idx];
    float2 o;
    o.x = xv.x * cs - xv.y * sn;
    o.y = xv.y * cs + xv.x * sn;
    ((float2*)out)[idx] = o;
}

// ---------------- SGEMM: C[M,N] = A[M,K] @ W[N,K]^T + bias (+res)(+relu) ----------------
// 128x128 block tile, BK=8, 256 threads, 8x8 per thread. M,N % 128 == 0, K % 8 == 0.
__global__ __launch_bounds__(256) void sgemm_kernel(const float* __restrict__ A,
                                                    const float* __restrict__ W,
                                                    const float* __restrict__ bias,
                                                    const float* __restrict__ res,
                                                    float* __restrict__ C,
                                                    int M, int N, int K, int flags) {
    __shared__ float As[8][128];
    __shared__ float Ws[8][128];
    int tid  = threadIdx.x;
    int row0 = blockIdx.y * 128;
    int col0 = blockIdx.x * 128;
    int lr = tid >> 1;           // 0..127
    int lc = (tid & 1) << 2;     // 0 or 4
    const float* Ap = A + (size_t)(row0 + lr) * K + lc;
    const float* Wp = W + (size_t)(col0 + lr) * K + lc;
    int tx = tid & 15, ty = tid >> 4;
    float acc[8][8];
    #pragma unroll
    for (int i = 0; i < 8; i++)
        #pragma unroll
        for (int j = 0; j < 8; j++) acc[i][j] = 0.f;

    for (int k0 = 0; k0 < K; k0 += 8) {
        float4 a = *(const float4*)(Ap + k0);
        float4 w = *(const float4*)(Wp + k0);
        As[lc+0][lr] = a.x; As[lc+1][lr] = a.y; As[lc+2][lr] = a.z; As[lc+3][lr] = a.w;
        Ws[lc+0][lr] = w.x; Ws[lc+1][lr] = w.y; Ws[lc+2][lr] = w.z; Ws[lc+3][lr] = w.w;
        __syncthreads();
        #pragma unroll
        for (int k = 0; k < 8; k++) {
            float rm[8], rn[8];
            *(float4*)(rm)     = *(const float4*)&As[k][ty*8];
            *(float4*)(rm + 4) = *(const float4*)&As[k][ty*8 + 4];
            *(float4*)(rn)     = *(const float4*)&Ws[k][tx*8];
            *(float4*)(rn + 4) = *(const float4*)&Ws[k][tx*8 + 4];
            #pragma unroll
            for (int i = 0; i < 8; i++)
                #pragma unroll
                for (int j = 0; j < 8; j++)
                    acc[i][j] += rm[i] * rn[j];
        }
        __syncthreads();
    }

    bool use_relu = (flags & 1) != 0;
    bool use_res  = (flags & 2) != 0;
    #pragma unroll
    for (int i = 0; i < 8; i++) {
        int r = row0 + ty * 8 + i;
        size_t base = (size_t)r * N + col0 + tx * 8;
        #pragma unroll
        for (int j = 0; j < 8; j += 4) {
            float4 o;
            o.x = acc[i][j+0] + bias[col0 + tx*8 + j + 0];
            o.y = acc[i][j+1] + bias[col0 + tx*8 + j + 1];
            o.z = acc[i][j+2] + bias[col0 + tx*8 + j + 2];
            o.w = acc[i][j+3] + bias[col0 + tx*8 + j + 3];
            if (use_res) {
                float4 rv = *(const float4*)(res + base + j);
                o.x += rv.x; o.y += rv.y; o.z += rv.z; o.w += rv.w;
            }
            if (use_relu) {
                o.x = fmaxf(o.x, 0.f); o.y = fmaxf(o.y, 0.f);
                o.z = fmaxf(o.z, 0.f); o.w = fmaxf(o.w, 0.f);
            }
            *(float4*)(C + base + j) = o;
        }
    }
}

// ---------------- Attention: one block per (b, h, q-row). Scores in smem. ----------------
__global__ __launch_bounds__(256) void attn_kernel(const float* __restrict__ Q,
                                                   const float* __restrict__ Kmat,
                                                   const float* __restrict__ Vmat,
                                                   float* __restrict__ O,
                                                   int Sq, int Sk, int causal) {
    __shared__ float sc[SMEMLEN];
    __shared__ float qv[HD];
    __shared__ float red[8];
    __shared__ float outp[4][HD];
    int qi = blockIdx.x, h = blockIdx.y, b = blockIdx.z;
    int tid = threadIdx.x, lane = tid & 31, wid = tid >> 5;

    const float* qrow = Q + ((size_t)(b * Sq + qi) * NH + h) * HD;
    if (tid < HD) qv[tid] = qrow[tid];
    __syncthreads();

    int kmax = causal ? (qi + 1) : Sk;

    // scores: warp per key
    for (int j = wid; j < kmax; j += 8) {
        const float* kr = Kmat + ((size_t)(b * Sk + j) * NH + h) * HD;
        float s = qv[lane] * kr[lane] + qv[lane + 32] * kr[lane + 32];
        #pragma unroll
        for (int o = 16; o; o >>= 1) s += __shfl_xor_sync(0xffffffffu, s, o);
        if (lane == 0) sc[j] = s * 0.125f;   // 1/sqrt(64)
    }
    __syncthreads();

    // softmax max
    float m = -1e30f;
    for (int j = tid; j < kmax; j += 256) m = fmaxf(m, sc[j]);
    #pragma unroll
    for (int o = 16; o; o >>= 1) m = fmaxf(m, __shfl_xor_sync(0xffffffffu, m, o));
    if (lane == 0) red[wid] = m;
    __syncthreads();
    float bm = -1e30f;
    #pragma unroll
    for (int w = 0; w < 8; w++) bm = fmaxf(bm, red[w]);
    __syncthreads();

    // exp + sum
    float psum = 0.f;
    for (int j = tid; j < kmax; j += 256) {
        float e = __expf(sc[j] - bm);
        sc[j] = e;
        psum += e;
    }
    #pragma unroll
    for (int o = 16; o; o >>= 1) psum += __shfl_xor_sync(0xffffffffu, psum, o);
    if (lane == 0) red[wid] = psum;
    __syncthreads();
    float denom = 0.f;
    #pragma unroll
    for (int w = 0; w < 8; w++) denom += red[w];
    float inv = 1.0f / denom;

    // weighted sum over V: 4 groups x 64 dims
    int g = tid >> 6;    // 0..3
    int d = tid & 63;
    float acc = 0.f;
    for (int j = g; j < kmax; j += 4)
        acc += sc[j] * Vmat[((size_t)(b * Sk + j) * NH + h) * HD + d];
    outp[g][d] = acc;
    __syncthreads();
    if (tid < HD) {
        float o = (outp[0][tid] + outp[1][tid] + outp[2][tid] + outp[3][tid]) * inv;
        O[((size_t)(b * Sq + qi) * NH + h) * HD + tid] = o;
    }
}

// ---------------- host orchestration ----------------
extern "C" void kernel_launch(void* const* d_in, const int* in_sizes, int n_in,
                              void* d_out, int out_size) {
    const float* tgt      = (const float*)d_in[0];
    const float* memory   = (const float*)d_in[1];
    const float* sa_in_w  = (const float*)d_in[2];
    const float* sa_in_b  = (const float*)d_in[3];
    const float* sa_out_w = (const float*)d_in[4];
    const float* sa_out_b = (const float*)d_in[5];
    const float* ca_in_w  = (const float*)d_in[6];
    const float* ca_in_b  = (const float*)d_in[7];
    const float* ca_out_w = (const float*)d_in[8];
    const float* ca_out_b = (const float*)d_in[9];
    const float* ff1_w    = (const float*)d_in[10];
    const float* ff1_b    = (const float*)d_in[11];
    const float* ff2_w    = (const float*)d_in[12];
    const float* ff2_b    = (const float*)d_in[13];
    const float* ln1_g    = (const float*)d_in[14];
    const float* ln1_b    = (const float*)d_in[15];
    const float* ln2_g    = (const float*)d_in[16];
    const float* ln2_b    = (const float*)d_in[17];
    const float* ln3_g    = (const float*)d_in[18];
    const float* ln3_b    = (const float*)d_in[19];
    float* out = (float*)d_out;

    float *p_h, *p_roped, *p_q, *p_k, *p_v, *p_attn, *p_x, *p_ffh;
    cudaGetSymbolAddress((void**)&p_h,     g_h);
    cudaGetSymbolAddress((void**)&p_roped, g_roped);
    cudaGetSymbolAddress((void**)&p_q,     g_q);
    cudaGetSymbolAddress((void**)&p_k,     g_k);
    cudaGetSymbolAddress((void**)&p_v,     g_v);
    cudaGetSymbolAddress((void**)&p_attn,  g_attn);
    cudaGetSymbolAddress((void**)&p_x,     g_x);
    cudaGetSymbolAddress((void**)&p_ffh,   g_ffh);

    dim3 gemm_nt_d(DMODEL / 128, NT / 128);      // (8, 50)
    dim3 gemm_mt_d(DMODEL / 128, MTOK / 128);    // (8, 256)
    dim3 gemm_ff1(DFF / 128, NT / 128);          // (32, 50)
    int rope_blocks = (NT * (DMODEL / 2) + 255) / 256;

    // ---- self-attention block ----
    ln_kernel<<<NT, 256>>>(tgt, ln1_g, ln1_b, p_h);
    rope_kernel<<<rope_blocks, 256>>>(p_h, p_roped);
    sgemm_kernel<<<gemm_nt_d, 256>>>(p_roped, sa_in_w,                        sa_in_b,              nullptr, p_q, NT, DMODEL, DMODEL, 0);
    sgemm_kernel<<<gemm_nt_d, 256>>>(p_roped, sa_in_w + (size_t)DMODEL*DMODEL,   sa_in_b + DMODEL,     nullptr, p_k, NT, DMODEL, DMODEL, 0);
    sgemm_kernel<<<gemm_nt_d, 256>>>(p_h,     sa_in_w + (size_t)2*DMODEL*DMODEL, sa_in_b + 2*DMODEL,   nullptr, p_v, NT, DMODEL, DMODEL, 0);
    attn_kernel<<<dim3(SQ, NH, BB), 256>>>(p_q, p_k, p_v, p_attn, SQ, SQ, 1);
    sgemm_kernel<<<gemm_nt_d, 256>>>(p_attn, sa_out_w, sa_out_b, tgt, p_x, NT, DMODEL, DMODEL, 2);

    // ---- cross-attention block ----
    ln_kernel<<<NT, 256>>>(p_x, ln2_g, ln2_b, p_h);
    sgemm_kernel<<<gemm_nt_d, 256>>>(p_h,    ca_in_w,                           ca_in_b,            nullptr, p_q, NT,   DMODEL, DMODEL, 0);
    sgemm_kernel<<<gemm_mt_d, 256>>>(memory, ca_in_w + (size_t)DMODEL*DMODEL,   ca_in_b + DMODEL,   nullptr, p_k, MTOK, DMODEL, DMODEL, 0);
    sgemm_kernel<<<gemm_mt_d, 256>>>(memory, ca_in_w + (size_t)2*DMODEL*DMODEL, ca_in_b + 2*DMODEL, nullptr, p_v, MTOK, DMODEL, DMODEL, 0);
    attn_kernel<<<dim3(SQ, NH, BB), 256>>>(p_q, p_k, p_v, p_attn, SQ, SMEMLEN, 0);
    sgemm_kernel<<<gemm_nt_d, 256>>>(p_attn, ca_out_w, ca_out_b, p_x, p_x, NT, DMODEL, DMODEL, 2);

    // ---- feed-forward block ----
    ln_kernel<<<NT, 256>>>(p_x, ln3_g, ln3_b, p_h);
    sgemm_kernel<<<gemm_ff1, 256>>>(p_h,   ff1_w, ff1_b, nullptr, p_ffh, NT, DFF, DMODEL, 1);
    sgemm_kernel<<<gemm_nt_d, 256>>>(p_ffh, ff2_w, ff2_b, p_x, out, NT, DMODEL, DFF, 2);
}

// round 2
// speedup vs baseline: 3.1458x; 3.1458x over previous
#include <cuda_runtime.h>
#include <math.h>

#define BB 32
#define SQ 200
#define SMEMLEN 1024
#define DMODEL 1024
#define NH 16
#define HD 64
#define DFF 4096
#define NT (BB*SQ)        // 6400 target tokens
#define MTOK (BB*SMEMLEN) // 32768 memory tokens
#define EPS 1e-5f

// ---------------- scratch ----------------
__device__ float g_h[NT*DMODEL];
__device__ float g_roped[NT*DMODEL];
__device__ float g_q[NT*DMODEL];
__device__ float g_k[MTOK*DMODEL];
__device__ float g_v[MTOK*DMODEL];
__device__ float g_attn[NT*DMODEL];
__device__ float g_x[NT*DMODEL];
__device__ float g_ffh[NT*DFF];

__device__ __forceinline__ unsigned f2tf32(float f) {
    unsigned r;
    asm("cvt.rna.tf32.f32 %0, %1;" : "=r"(r) : "f"(f));
    return r;
}

// ---------------- LayerNorm ----------------
__global__ __launch_bounds__(256) void ln_kernel(const float* __restrict__ x,
                                                 const float* __restrict__ g,
                                                 const float* __restrict__ b,
                                                 float* __restrict__ out) {
    __shared__ float rs[8], rss[8];
    int t = blockIdx.x;
    int tid = threadIdx.x;
    const float4* xr = (const float4*)(x + (size_t)t * DMODEL);
    float4 v = xr[tid];
    float s  = v.x + v.y + v.z + v.w;
    float ss = v.x*v.x + v.y*v.y + v.z*v.z + v.w*v.w;
    #pragma unroll
    for (int o = 16; o; o >>= 1) {
        s  += __shfl_xor_sync(0xffffffffu, s, o);
        ss += __shfl_xor_sync(0xffffffffu, ss, o);
    }
    int lane = tid & 31, wid = tid >> 5;
    if (lane == 0) { rs[wid] = s; rss[wid] = ss; }
    __syncthreads();
    float ts = 0.f, tss = 0.f;
    #pragma unroll
    for (int w = 0; w < 8; w++) { ts += rs[w]; tss += rss[w]; }
    float mu  = ts * (1.0f / DMODEL);
    float var = tss * (1.0f / DMODEL) - mu * mu;
    float r   = rsqrtf(var + EPS);
    float4 gv = ((const float4*)g)[tid];
    float4 bv = ((const float4*)b)[tid];
    float4 o;
    o.x = (v.x - mu) * r * gv.x + bv.x;
    o.y = (v.y - mu) * r * gv.y + bv.y;
    o.z = (v.z - mu) * r * gv.z + bv.z;
    o.w = (v.w - mu) * r * gv.w + bv.w;
    ((float4*)(out + (size_t)t * DMODEL))[tid] = o;
}

// ---------------- RoPE ----------------
__global__ void rope_kernel(const float* __restrict__ in, float* __restrict__ out) {
    int idx = blockIdx.x * blockDim.x + threadIdx.x;
    if (idx >= NT * (DMODEL / 2)) return;
    int t = idx / (DMODEL / 2);
    int p = idx - t * (DMODEL / 2);
    int i = p & 31;
    int s = t % SQ;
    float freq = __expf(-9.210340371976184f * (2.0f * i) * (1.0f / 64.0f));
    float ang = (float)s * freq;
    float sn, cs;
    sincosf(ang, &sn, &cs);
    const float2 xv = ((const float2*)in)[idx];
    float2 o;
    o.x = xv.x * cs - xv.y * sn;
    o.y = xv.y * cs + xv.x * sn;
    ((float2*)out)[idx] = o;
}

// ---------------- tf32 tensor-core GEMM ----------------
// C[M,N] = A[M,K] @ W[N,K]^T + bias (+res)(+relu)
// 128x128 tile, BK=16, 256 threads / 8 warps, warp tile 32x64 via m16n8k8 tf32 mma.
#define GPAD 20
__global__ __launch_bounds__(256) void sgemm_tf32(const float* __restrict__ A,
                                                  const float* __restrict__ W,
                                                  const float* __restrict__ bias,
                                                  const float* __restrict__ res,
                                                  float* __restrict__ C,
                                                  int M, int N, int K, int flags) {
    __shared__ unsigned As[128][GPAD];
    __shared__ unsigned Ws[128][GPAD];
    int tid = threadIdx.x;
    int wid = tid >> 5, lane = tid & 31;
    int gid = lane >> 2, tig = lane & 3;
    int row0 = blockIdx.y * 128;
    int col0 = blockIdx.x * 128;
    int wm = (wid & 3) * 32;
    int wn = (wid >> 2) * 64;

    // gmem load mapping: each thread loads 8 floats of A and W per iter
    int lm = tid >> 1;            // 0..127 row within tile
    int lk = (tid & 1) * 8;       // 0 or 8
    const float* Ap = A + (size_t)(row0 + lm) * K + lk;
    const float* Wp = W + (size_t)(col0 + lm) * K + lk;

    float c[2][8][4];
    #pragma unroll
    for (int mi = 0; mi < 2; mi++)
        #pragma unroll
        for (int ni = 0; ni < 8; ni++)
            #pragma unroll
            for (int q = 0; q < 4; q++) c[mi][ni][q] = 0.f;

    float4 pa0 = *(const float4*)(Ap);
    float4 pa1 = *(const float4*)(Ap + 4);
    float4 pw0 = *(const float4*)(Wp);
    float4 pw1 = *(const float4*)(Wp + 4);

    for (int k0 = 0; k0 < K; k0 += 16) {
        As[lm][lk+0] = f2tf32(pa0.x); As[lm][lk+1] = f2tf32(pa0.y);
        As[lm][lk+2] = f2tf32(pa0.z); As[lm][lk+3] = f2tf32(pa0.w);
        As[lm][lk+4] = f2tf32(pa1.x); As[lm][lk+5] = f2tf32(pa1.y);
        As[lm][lk+6] = f2tf32(pa1.z); As[lm][lk+7] = f2tf32(pa1.w);
        Ws[lm][lk+0] = f2tf32(pw0.x); Ws[lm][lk+1] = f2tf32(pw0.y);
        Ws[lm][lk+2] = f2tf32(pw0.z); Ws[lm][lk+3] = f2tf32(pw0.w);
        Ws[lm][lk+4] = f2tf32(pw1.x); Ws[lm][lk+5] = f2tf32(pw1.y);
        Ws[lm][lk+6] = f2tf32(pw1.z); Ws[lm][lk+7] = f2tf32(pw1.w);
        __syncthreads();

        if (k0 + 16 < K) {
            pa0 = *(const float4*)(Ap + k0 + 16);
            pa1 = *(const float4*)(Ap + k0 + 20);
            pw0 = *(const float4*)(Wp + k0 + 16);
            pw1 = *(const float4*)(Wp + k0 + 20);
        }

        #pragma unroll
        for (int ks = 0; ks < 2; ks++) {
            int kb = ks * 8;
            unsigned af[2][4];
            #pragma unroll
            for (int mi = 0; mi < 2; mi++) {
                int r = wm + mi * 16 + gid;
                af[mi][0] = As[r    ][kb + tig];
                af[mi][1] = As[r + 8][kb + tig];
                af[mi][2] = As[r    ][kb + tig + 4];
                af[mi][3] = As[r + 8][kb + tig + 4];
            }
            unsigned bf[8][2];
            #pragma unroll
            for (int ni = 0; ni < 8; ni++) {
                int r = wn + ni * 8 + gid;
                bf[ni][0] = Ws[r][kb + tig];
                bf[ni][1] = Ws[r][kb + tig + 4];
            }
            #pragma unroll
            for (int mi = 0; mi < 2; mi++)
                #pragma unroll
                for (int ni = 0; ni < 8; ni++) {
                    asm volatile(
                        "mma.sync.aligned.m16n8k8.row.col.f32.tf32.tf32.f32 "
                        "{%0,%1,%2,%3}, {%4,%5,%6,%7}, {%8,%9}, {%0,%1,%2,%3};"
                        : "+f"(c[mi][ni][0]), "+f"(c[mi][ni][1]),
                          "+f"(c[mi][ni][2]), "+f"(c[mi][ni][3])
                        : "r"(af[mi][0]), "r"(af[mi][1]), "r"(af[mi][2]), "r"(af[mi][3]),
                          "r"(bf[ni][0]), "r"(bf[ni][1]));
                }
        }
        __syncthreads();
    }

    bool use_relu = (flags & 1) != 0;
    bool use_res  = (flags & 2) != 0;
    #pragma unroll
    for (int mi = 0; mi < 2; mi++) {
        #pragma unroll
        for (int ni = 0; ni < 8; ni++) {
            int colg = col0 + wn + ni * 8 + tig * 2;
            int r0 = row0 + wm + mi * 16 + gid;
            int r1 = r0 + 8;
            float b0 = bias[colg], b1 = bias[colg + 1];
            float2 o0, o1;
            o0.x = c[mi][ni][0] + b0; o0.y = c[mi][ni][1] + b1;
            o1.x = c[mi][ni][2] + b0; o1.y = c[mi][ni][3] + b1;
            size_t i0 = (size_t)r0 * N + colg;
            size_t i1 = (size_t)r1 * N + colg;
            if (use_res) {
                float2 rv0 = *(const float2*)(res + i0);
                float2 rv1 = *(const float2*)(res + i1);
                o0.x += rv0.x; o0.y += rv0.y;
                o1.x += rv1.x; o1.y += rv1.y;
            }
            if (use_relu) {
                o0.x = fmaxf(o0.x, 0.f); o0.y = fmaxf(o0.y, 0.f);
                o1.x = fmaxf(o1.x, 0.f); o1.y = fmaxf(o1.y, 0.f);
            }
            *(float2*)(C + i0) = o0;
            *(float2*)(C + i1) = o1;
        }
    }
}

// ---------------- tiled flash attention ----------------
// block = (q_tile of 64, h, b). 256 threads. Online softmax, fp32 scalar math.
// thread (qg = tid>>4, j = tid&15): owns q rows qg*4..+3; S-phase k cols {j,j+16,j+32,j+48};
// PV-phase d cols j*4..+3.
#define ATQ 64
#define ATK 64
#define APAD 68

__global__ __launch_bounds__(256) void attn2_kernel(const float* __restrict__ Q,
                                                    const float* __restrict__ Km,
                                                    const float* __restrict__ Vm,
                                                    float* __restrict__ O,
                                                    int Sq, int Sk, int causal) {
    extern __shared__ float sm[];
    float* Qs = sm;                       // [64][APAD]
    float* Ks = sm + ATQ * APAD;
    float* Vs = sm + 2 * ATQ * APAD;
    float* Ss = sm + 3 * ATQ * APAD;      // P transposed: [k][q]

    int qt = blockIdx.x, h = blockIdx.y, b = blockIdx.z;
    int tid = threadIdx.x;
    int qg = tid >> 4;     // 0..15
    int j  = tid & 15;

    // load Q tile (zero-fill invalid rows)
    {
        int qr = tid >> 2;
        int qgl = qt * ATQ + qr;
        int dq = (tid & 3) * 16;
        const float* src = Q + (((size_t)b * Sq + qgl) * NH + h) * (size_t)HD + dq;
        float4 z = {0.f, 0.f, 0.f, 0.f};
        #pragma unroll
        for (int i = 0; i < 4; i++) {
            float4 v = (qgl < Sq) ? *(const float4*)(src + i * 4) : z;
            *(float4*)&Qs[qr * APAD + dq + i * 4] = v;
        }
    }

    float m_i[4], l_i[4], acc[4][4];
    #pragma unroll
    for (int qi = 0; qi < 4; qi++) {
        m_i[qi] = -1e30f; l_i[qi] = 0.f;
        #pragma unroll
        for (int di = 0; di < 4; di++) acc[qi][di] = 0.f;
    }

    int q_hi = qt * ATQ + ATQ - 1;
    int keff = causal ? min(q_hi + 1, Sk) : Sk;
    int ntiles = (keff + ATK - 1) / ATK;

    // prefetch tile 0
    int kr = tid >> 2;
    int dq = (tid & 3) * 16;
    float4 pk[4], pv[4];
    {
        int kg = kr;
        bool ok = kg < Sk;
        const float* ksrc = Km + (((size_t)b * Sk + kg) * NH + h) * (size_t)HD + dq;
        const float* vsrc = Vm + (((size_t)b * Sk + kg) * NH + h) * (size_t)HD + dq;
        float4 z = {0.f, 0.f, 0.f, 0.f};
        #pragma unroll
        for (int i = 0; i < 4; i++) {
            pk[i] = ok ? *(const float4*)(ksrc + i * 4) : z;
            pv[i] = ok ? *(const float4*)(vsrc + i * 4) : z;
        }
    }

    for (int kt = 0; kt < ntiles; kt++) {
        #pragma unroll
        for (int i = 0; i < 4; i++) {
            *(float4*)&Ks[kr * APAD + dq + i * 4] = pk[i];
            *(float4*)&Vs[kr * APAD + dq + i * 4] = pv[i];
        }
        __syncthreads();

        if (kt + 1 < ntiles) {
            int kg = (kt + 1) * ATK + kr;
            bool ok = kg < Sk;
            const float* ksrc = Km + (((size_t)b * Sk + kg) * NH + h) * (size_t)HD + dq;
            const float* vsrc = Vm + (((size_t)b * Sk + kg) * NH + h) * (size_t)HD + dq;
            float4 z = {0.f, 0.f, 0.f, 0.f};
            #pragma unroll
            for (int i = 0; i < 4; i++) {
                pk[i] = ok ? *(const float4*)(ksrc + i * 4) : z;
                pv[i] = ok ? *(const float4*)(vsrc + i * 4) : z;
            }
        }

        // S phase
        float s[4][4];
        #pragma unroll
        for (int qi = 0; qi < 4; qi++)
            #pragma unroll
            for (int ki = 0; ki < 4; ki++) s[qi][ki] = 0.f;

        #pragma unroll
        for (int d0 = 0; d0 < HD; d0 += 4) {
            float4 q4[4], k4[4];
            #pragma unroll
            for (int qi = 0; qi < 4; qi++)
                q4[qi] = *(const float4*)&Qs[(qg * 4 + qi) * APAD + d0];
            #pragma unroll
            for (int ki = 0; ki < 4; ki++)
                k4[ki] = *(const float4*)&Ks[(j + 16 * ki) * APAD + d0];
            #pragma unroll
            for (int qi = 0; qi < 4; qi++)
                #pragma unroll
                for (int ki = 0; ki < 4; ki++) {
                    s[qi][ki] += q4[qi].x * k4[ki].x + q4[qi].y * k4[ki].y
                               + q4[qi].z * k4[ki].z + q4[qi].w * k4[ki].w;
                }
        }

        // mask + softmax update
        #pragma unroll
        for (int qi = 0; qi < 4; qi++) {
            int qgl = qt * ATQ + qg * 4 + qi;
            int kvalid = causal ? min(qgl + 1, Sk) : Sk;
            #pragma unroll
            for (int ki = 0; ki < 4; ki++) {
                int kg = kt * ATK + j + 16 * ki;
                s[qi][ki] = (kg < kvalid) ? s[qi][ki] * 0.125f : -1e30f;
            }
            float tm = fmaxf(fmaxf(s[qi][0], s[qi][1]), fmaxf(s[qi][2], s[qi][3]));
            #pragma unroll
            for (int off = 1; off < 16; off <<= 1)
                tm = fmaxf(tm, __shfl_xor_sync(0xffffffffu, tm, off));
            float mn = fmaxf(m_i[qi], tm);
            float scale = __expf(m_i[qi] - mn);
            float ps = 0.f;
            #pragma unroll
            for (int ki = 0; ki < 4; ki++) {
                float p = __expf(s[qi][ki] - mn);
                s[qi][ki] = p;
                ps += p;
            }
            #pragma unroll
            for (int off = 1; off < 16; off <<= 1)
                ps += __shfl_xor_sync(0xffffffffu, ps, off);
            l_i[qi] = l_i[qi] * scale + ps;
            m_i[qi] = mn;
            #pragma unroll
            for (int di = 0; di < 4; di++) acc[qi][di] *= scale;
        }

        // store P transposed
        #pragma unroll
        for (int ki = 0; ki < 4; ki++)
            #pragma unroll
            for (int qi = 0; qi < 4; qi++)
                Ss[(j + 16 * ki) * APAD + qg * 4 + qi] = s[qi][ki];
        __syncthreads();

        // PV
        #pragma unroll 8
        for (int k = 0; k < ATK; k++) {
            float4 p4 = *(const float4*)&Ss[k * APAD + qg * 4];
            float4 v4 = *(const float4*)&Vs[k * APAD + j * 4];
            acc[0][0] += p4.x * v4.x; acc[0][1] += p4.x * v4.y;
            acc[0][2] += p4.x * v4.z; acc[0][3] += p4.x * v4.w;
            acc[1][0] += p4.y * v4.x; acc[1][1] += p4.y * v4.y;
            acc[1][2] += p4.y * v4.z; acc[1][3] += p4.y * v4.w;
            acc[2][0] += p4.z * v4.x; acc[2][1] += p4.z * v4.y;
            acc[2][2] += p4.z * v4.z; acc[2][3] += p4.z * v4.w;
            acc[3][0] += p4.w * v4.x; acc[3][1] += p4.w * v4.y;
            acc[3][2] += p4.w * v4.z; acc[3][3] += p4.w * v4.w;
        }
        __syncthreads();
    }

    // write out
    int dd = j * 4;
    #pragma unroll
    for (int qi = 0; qi < 4; qi++) {
        int qgl = qt * ATQ + qg * 4 + qi;
        if (qgl < Sq) {
            float inv = 1.0f / l_i[qi];
            float4 o;
            o.x = acc[qi][0] * inv; o.y = acc[qi][1] * inv;
            o.z = acc[qi][2] * inv; o.w = acc[qi][3] * inv;
            *(float4*)&O[(((size_t)b * Sq + qgl) * NH + h) * (size_t)HD + dd] = o;
        }
    }
}

// ---------------- host orchestration ----------------
extern "C" void kernel_launch(void* const* d_in, const int* in_sizes, int n_in,
                              void* d_out, int out_size) {
    const float* tgt      = (const float*)d_in[0];
    const float* memory   = (const float*)d_in[1];
    const float* sa_in_w  = (const float*)d_in[2];
    const float* sa_in_b  = (const float*)d_in[3];
    const float* sa_out_w = (const float*)d_in[4];
    const float* sa_out_b = (const float*)d_in[5];
    const float* ca_in_w  = (const float*)d_in[6];
    const float* ca_in_b  = (const float*)d_in[7];
    const float* ca_out_w = (const float*)d_in[8];
    const float* ca_out_b = (const float*)d_in[9];
    const float* ff1_w    = (const float*)d_in[10];
    const float* ff1_b    = (const float*)d_in[11];
    const float* ff2_w    = (const float*)d_in[12];
    const float* ff2_b    = (const float*)d_in[13];
    const float* ln1_g    = (const float*)d_in[14];
    const float* ln1_b    = (const float*)d_in[15];
    const float* ln2_g    = (const float*)d_in[16];
    const float* ln2_b    = (const float*)d_in[17];
    const float* ln3_g    = (const float*)d_in[18];
    const float* ln3_b    = (const float*)d_in[19];
    float* out = (float*)d_out;

    float *p_h, *p_roped, *p_q, *p_k, *p_v, *p_attn, *p_x, *p_ffh;
    cudaGetSymbolAddress((void**)&p_h,     g_h);
    cudaGetSymbolAddress((void**)&p_roped, g_roped);
    cudaGetSymbolAddress((void**)&p_q,     g_q);
    cudaGetSymbolAddress((void**)&p_k,     g_k);
    cudaGetSymbolAddress((void**)&p_v,     g_v);
    cudaGetSymbolAddress((void**)&p_attn,  g_attn);
    cudaGetSymbolAddress((void**)&p_x,     g_x);
    cudaGetSymbolAddress((void**)&p_ffh,   g_ffh);

    static int smem_set = 0;
    int attn_smem = 4 * ATQ * APAD * sizeof(float);   // ~69.6 KB
    if (!smem_set) {
        cudaFuncSetAttribute(attn2_kernel, cudaFuncAttributeMaxDynamicSharedMemorySize, attn_smem);
        smem_set = 1;
    }

    dim3 gemm_nt_d(DMODEL / 128, NT / 128);      // (8, 50)
    dim3 gemm_mt_d(DMODEL / 128, MTOK / 128);    // (8, 256)
    dim3 gemm_ff1(DFF / 128, NT / 128);          // (32, 50)
    int rope_blocks = (NT * (DMODEL / 2) + 255) / 256;
    int qtiles = (SQ + ATQ - 1) / ATQ;           // 4

    // ---- self-attention block ----
    ln_kernel<<<NT, 256>>>(tgt, ln1_g, ln1_b, p_h);
    rope_kernel<<<rope_blocks, 256>>>(p_h, p_roped);
    sgemm_tf32<<<gemm_nt_d, 256>>>(p_roped, sa_in_w,                           sa_in_b,            nullptr, p_q, NT, DMODEL, DMODEL, 0);
    sgemm_tf32<<<gemm_nt_d, 256>>>(p_roped, sa_in_w + (size_t)DMODEL*DMODEL,   sa_in_b + DMODEL,   nullptr, p_k, NT, DMODEL, DMODEL, 0);
    sgemm_tf32<<<gemm_nt_d, 256>>>(p_h,     sa_in_w + (size_t)2*DMODEL*DMODEL, sa_in_b + 2*DMODEL, nullptr, p_v, NT, DMODEL, DMODEL, 0);
    attn2_kernel<<<dim3(qtiles, NH, BB), 256, attn_smem>>>(p_q, p_k, p_v, p_attn, SQ, SQ, 1);
    sgemm_tf32<<<gemm_nt_d, 256>>>(p_attn, sa_out_w, sa_out_b, tgt, p_x, NT, DMODEL, DMODEL, 2);

    // ---- cross-attention block ----
    ln_kernel<<<NT, 256>>>(p_x, ln2_g, ln2_b, p_h);
    sgemm_tf32<<<gemm_nt_d, 256>>>(p_h,    ca_in_w,                           ca_in_b,            nullptr, p_q, NT,   DMODEL, DMODEL, 0);
    sgemm_tf32<<<gemm_mt_d, 256>>>(memory, ca_in_w + (size_t)DMODEL*DMODEL,   ca_in_b + DMODEL,   nullptr, p_k, MTOK, DMODEL, DMODEL, 0);
    sgemm_tf32<<<gemm_mt_d, 256>>>(memory, ca_in_w + (size_t)2*DMODEL*DMODEL, ca_in_b + 2*DMODEL, nullptr, p_v, MTOK, DMODEL, DMODEL, 0);
    attn2_kernel<<<dim3(qtiles, NH, BB), 256, attn_smem>>>(p_q, p_k, p_v, p_attn, SQ, SMEMLEN, 0);
    sgemm_tf32<<<gemm_nt_d, 256>>>(p_attn, ca_out_w, ca_out_b, p_x, p_x, NT, DMODEL, DMODEL, 2);

    // ---- feed-forward block ----
    ln_kernel<<<NT, 256>>>(p_x, ln3_g, ln3_b, p_h);
    sgemm_tf32<<<gemm_ff1, 256>>>(p_h,   ff1_w, ff1_b, nullptr, p_ffh, NT, DFF, DMODEL, 1);
    sgemm_tf32<<<gemm_nt_d, 256>>>(p_ffh, ff2_w, ff2_b, p_x, out, NT, DMODEL, DFF, 2);
}

// round 3
// speedup vs baseline: 4.2551x; 1.3526x over previous
#include <cuda_runtime.h>
#include <math.h>

#define BB 32
#define SQ 200
#define SMEMLEN 1024
#define DMODEL 1024
#define NH 16
#define HD 64
#define DFF 4096
#define NT (BB*SQ)        // 6400 target tokens
#define MTOK (BB*SMEMLEN) // 32768 memory tokens
#define EPS 1e-5f

// ---------------- scratch ----------------
__device__ float g_h[NT*DMODEL];
__device__ float g_roped[NT*DMODEL];
__device__ float g_q[NT*DMODEL];
__device__ float g_k[MTOK*DMODEL];
__device__ float g_v[MTOK*DMODEL];
__device__ float g_attn[NT*DMODEL];
__device__ float g_x[NT*DMODEL];
__device__ float g_ffh[NT*DFF];

// ---------------- LayerNorm ----------------
__global__ __launch_bounds__(256) void ln_kernel(const float* __restrict__ x,
                                                 const float* __restrict__ g,
                                                 const float* __restrict__ b,
                                                 float* __restrict__ out) {
    __shared__ float rs[8], rss[8];
    int t = blockIdx.x;
    int tid = threadIdx.x;
    const float4* xr = (const float4*)(x + (size_t)t * DMODEL);
    float4 v = xr[tid];
    float s  = v.x + v.y + v.z + v.w;
    float ss = v.x*v.x + v.y*v.y + v.z*v.z + v.w*v.w;
    #pragma unroll
    for (int o = 16; o; o >>= 1) {
        s  += __shfl_xor_sync(0xffffffffu, s, o);
        ss += __shfl_xor_sync(0xffffffffu, ss, o);
    }
    int lane = tid & 31, wid = tid >> 5;
    if (lane == 0) { rs[wid] = s; rss[wid] = ss; }
    __syncthreads();
    float ts = 0.f, tss = 0.f;
    #pragma unroll
    for (int w = 0; w < 8; w++) { ts += rs[w]; tss += rss[w]; }
    float mu  = ts * (1.0f / DMODEL);
    float var = tss * (1.0f / DMODEL) - mu * mu;
    float r   = rsqrtf(var + EPS);
    float4 gv = ((const float4*)g)[tid];
    float4 bv = ((const float4*)b)[tid];
    float4 o;
    o.x = (v.x - mu) * r * gv.x + bv.x;
    o.y = (v.y - mu) * r * gv.y + bv.y;
    o.z = (v.z - mu) * r * gv.z + bv.z;
    o.w = (v.w - mu) * r * gv.w + bv.w;
    ((float4*)(out + (size_t)t * DMODEL))[tid] = o;
}

// ---------------- RoPE ----------------
__global__ void rope_kernel(const float* __restrict__ in, float* __restrict__ out) {
    int idx = blockIdx.x * blockDim.x + threadIdx.x;
    if (idx >= NT * (DMODEL / 2)) return;
    int t = idx / (DMODEL / 2);
    int p = idx - t * (DMODEL / 2);
    int i = p & 31;
    int s = t % SQ;
    float freq = __expf(-9.210340371976184f * (2.0f * i) * (1.0f / 64.0f));
    float ang = (float)s * freq;
    float sn, cs;
    sincosf(ang, &sn, &cs);
    const float2 xv = ((const float2*)in)[idx];
    float2 o;
    o.x = xv.x * cs - xv.y * sn;
    o.y = xv.y * cs + xv.x * sn;
    ((float2*)out)[idx] = o;
}

// ---------------- tf32 tensor-core GEMM (cp.async + ldmatrix) ----------------
// C[M,N] = A[M,K] @ W[N,K]^T + bias (+res)(+relu)
// 128x128 tile, BK=32, 2-stage cp.async pipeline, 8 warps, warp tile 32x64.
#define BK 32
#define SPAD 36
#define STAGEF (2 * 128 * SPAD)          // floats per stage (A+W)
#define GSMEM  (2 * STAGEF * 4)          // bytes total (73728)

__device__ __forceinline__ void cpa16(unsigned dst, const void* src) {
    asm volatile("cp.async.cg.shared.global [%0], [%1], 16;\n" :: "r"(dst), "l"(src));
}
__device__ __forceinline__ void ldsm4(unsigned& r0, unsigned& r1, unsigned& r2, unsigned& r3,
                                      unsigned a) {
    asm volatile("ldmatrix.sync.aligned.m8n8.x4.shared.b16 {%0,%1,%2,%3}, [%4];"
                 : "=r"(r0), "=r"(r1), "=r"(r2), "=r"(r3) : "r"(a));
}

__global__ __launch_bounds__(256) void sgemm_tf32(const float* __restrict__ A,
                                                  const float* __restrict__ W,
                                                  const float* __restrict__ bias,
                                                  const float* __restrict__ res,
                                                  float* __restrict__ C,
                                                  int M, int N, int K, int flags) {
    extern __shared__ float smx[];
    int tid = threadIdx.x;
    int wid = tid >> 5, lane = tid & 31;
    int gid = lane >> 2, tig = lane & 3;
    int row0 = blockIdx.y * 128;
    int col0 = blockIdx.x * 128;
    int wm = (wid & 3) * 32;
    int wn = (wid >> 2) * 64;

    unsigned sbase = (unsigned)__cvta_generic_to_shared(smx);
    unsigned stgA[2], stgW[2];
    stgA[0] = sbase;
    stgW[0] = sbase + 128 * SPAD * 4;
    stgA[1] = sbase + STAGEF * 4;
    stgW[1] = stgA[1] + 128 * SPAD * 4;

    // loader mapping: 32 rows x (8 chunks of 16B) per wave, 4 waves
    int lr  = tid >> 3;           // 0..31
    int lkc = (tid & 7) * 4;      // 0,4,...,28
    const float* Ab = A + (size_t)(row0 + lr) * K + lkc;
    const float* Wb = W + (size_t)(col0 + lr) * K + lkc;

    float c[2][8][4];
    #pragma unroll
    for (int mi = 0; mi < 2; mi++)
        #pragma unroll
        for (int ni = 0; ni < 8; ni++)
            #pragma unroll
            for (int q = 0; q < 4; q++) c[mi][ni][q] = 0.f;

    int nk = K / BK;

    // prologue: stage 0
    {
        #pragma unroll
        for (int w = 0; w < 4; w++) {
            unsigned soff = ((lr + 32 * w) * SPAD + lkc) * 4;
            cpa16(stgA[0] + soff, Ab + (size_t)(32 * w) * K);
            cpa16(stgW[0] + soff, Wb + (size_t)(32 * w) * K);
        }
        asm volatile("cp.async.commit_group;\n");
    }

    // fragment address components
    int lrow = lane & 15;
    int lcol = (lane >> 4) * 4;

    for (int kt = 0; kt < nk; kt++) {
        if (kt + 1 < nk) {
            int st = (kt + 1) & 1;
            int k0 = (kt + 1) * BK;
            #pragma unroll
            for (int w = 0; w < 4; w++) {
                unsigned soff = ((lr + 32 * w) * SPAD + lkc) * 4;
                cpa16(stgA[st] + soff, Ab + (size_t)(32 * w) * K + k0);
                cpa16(stgW[st] + soff, Wb + (size_t)(32 * w) * K + k0);
            }
            asm volatile("cp.async.commit_group;\n");
            asm volatile("cp.async.wait_group 1;\n");
        } else {
            asm volatile("cp.async.wait_group 0;\n");
        }
        __syncthreads();

        int st = kt & 1;
        unsigned sAu = stgA[st];
        unsigned sWu = stgW[st];

        #pragma unroll
        for (int ks = 0; ks < 4; ks++) {
            int kb = ks * 8;
            unsigned af[2][4];
            #pragma unroll
            for (int mi = 0; mi < 2; mi++)
                ldsm4(af[mi][0], af[mi][1], af[mi][2], af[mi][3],
                      sAu + ((wm + mi * 16 + lrow) * SPAD + kb + lcol) * 4);
            unsigned bf[4][4];
            #pragma unroll
            for (int p = 0; p < 4; p++)
                ldsm4(bf[p][0], bf[p][1], bf[p][2], bf[p][3],
                      sWu + ((wn + p * 16 + lrow) * SPAD + kb + lcol) * 4);
            #pragma unroll
            for (int mi = 0; mi < 2; mi++)
                #pragma unroll
                for (int p = 0; p < 4; p++) {
                    asm volatile(
                        "mma.sync.aligned.m16n8k8.row.col.f32.tf32.tf32.f32 "
                        "{%0,%1,%2,%3}, {%4,%5,%6,%7}, {%8,%9}, {%0,%1,%2,%3};"
                        : "+f"(c[mi][2*p][0]), "+f"(c[mi][2*p][1]),
                          "+f"(c[mi][2*p][2]), "+f"(c[mi][2*p][3])
                        : "r"(af[mi][0]), "r"(af[mi][1]), "r"(af[mi][2]), "r"(af[mi][3]),
                          "r"(bf[p][0]), "r"(bf[p][2]));
                    asm volatile(
                        "mma.sync.aligned.m16n8k8.row.col.f32.tf32.tf32.f32 "
                        "{%0,%1,%2,%3}, {%4,%5,%6,%7}, {%8,%9}, {%0,%1,%2,%3};"
                        : "+f"(c[mi][2*p+1][0]), "+f"(c[mi][2*p+1][1]),
                          "+f"(c[mi][2*p+1][2]), "+f"(c[mi][2*p+1][3])
                        : "r"(af[mi][0]), "r"(af[mi][1]), "r"(af[mi][2]), "r"(af[mi][3]),
                          "r"(bf[p][1]), "r"(bf[p][3]));
                }
        }
        __syncthreads();
    }

    bool use_relu = (flags & 1) != 0;
    bool use_res  = (flags & 2) != 0;
    #pragma unroll
    for (int mi = 0; mi < 2; mi++) {
        #pragma unroll
        for (int ni = 0; ni < 8; ni++) {
            int colg = col0 + wn + ni * 8 + tig * 2;
            int r0 = row0 + wm + mi * 16 + gid;
            int r1 = r0 + 8;
            float b0 = bias[colg], b1 = bias[colg + 1];
            float2 o0, o1;
            o0.x = c[mi][ni][0] + b0; o0.y = c[mi][ni][1] + b1;
            o1.x = c[mi][ni][2] + b0; o1.y = c[mi][ni][3] + b1;
            size_t i0 = (size_t)r0 * N + colg;
            size_t i1 = (size_t)r1 * N + colg;
            if (use_res) {
                float2 rv0 = *(const float2*)(res + i0);
                float2 rv1 = *(const float2*)(res + i1);
                o0.x += rv0.x; o0.y += rv0.y;
                o1.x += rv1.x; o1.y += rv1.y;
            }
            if (use_relu) {
                o0.x = fmaxf(o0.x, 0.f); o0.y = fmaxf(o0.y, 0.f);
                o1.x = fmaxf(o1.x, 0.f); o1.y = fmaxf(o1.y, 0.f);
            }
            *(float2*)(C + i0) = o0;
            *(float2*)(C + i1) = o1;
        }
    }
}

// ---------------- tiled flash attention ----------------
#define ATQ 64
#define ATK 64
#define APAD 68

__global__ __launch_bounds__(256) void attn2_kernel(const float* __restrict__ Q,
                                                    const float* __restrict__ Km,
                                                    const float* __restrict__ Vm,
                                                    float* __restrict__ O,
                                                    int Sq, int Sk, int causal) {
    extern __shared__ float sm[];
    float* Qs = sm;
    float* Ks = sm + ATQ * APAD;
    float* Vs = sm + 2 * ATQ * APAD;
    float* Ss = sm + 3 * ATQ * APAD;

    int qt = blockIdx.x, h = blockIdx.y, b = blockIdx.z;
    int tid = threadIdx.x;
    int qg = tid >> 4;
    int j  = tid & 15;

    {
        int qr = tid >> 2;
        int qgl = qt * ATQ + qr;
        int dq = (tid & 3) * 16;
        const float* src = Q + (((size_t)b * Sq + qgl) * NH + h) * (size_t)HD + dq;
        float4 z = {0.f, 0.f, 0.f, 0.f};
        #pragma unroll
        for (int i = 0; i < 4; i++) {
            float4 v = (qgl < Sq) ? *(const float4*)(src + i * 4) : z;
            *(float4*)&Qs[qr * APAD + dq + i * 4] = v;
        }
    }

    float m_i[4], l_i[4], acc[4][4];
    #pragma unroll
    for (int qi = 0; qi < 4; qi++) {
        m_i[qi] = -1e30f; l_i[qi] = 0.f;
        #pragma unroll
        for (int di = 0; di < 4; di++) acc[qi][di] = 0.f;
    }

    int q_hi = qt * ATQ + ATQ - 1;
    int keff = causal ? min(q_hi + 1, Sk) : Sk;
    int ntiles = (keff + ATK - 1) / ATK;

    int kr = tid >> 2;
    int dq = (tid & 3) * 16;
    float4 pk[4], pv[4];
    {
        int kg = kr;
        bool ok = kg < Sk;
        const float* ksrc = Km + (((size_t)b * Sk + kg) * NH + h) * (size_t)HD + dq;
        const float* vsrc = Vm + (((size_t)b * Sk + kg) * NH + h) * (size_t)HD + dq;
        float4 z = {0.f, 0.f, 0.f, 0.f};
        #pragma unroll
        for (int i = 0; i < 4; i++) {
            pk[i] = ok ? *(const float4*)(ksrc + i * 4) : z;
            pv[i] = ok ? *(const float4*)(vsrc + i * 4) : z;
        }
    }

    for (int kt = 0; kt < ntiles; kt++) {
        #pragma unroll
        for (int i = 0; i < 4; i++) {
            *(float4*)&Ks[kr * APAD + dq + i * 4] = pk[i];
            *(float4*)&Vs[kr * APAD + dq + i * 4] = pv[i];
        }
        __syncthreads();

        if (kt + 1 < ntiles) {
            int kg = (kt + 1) * ATK + kr;
            bool ok = kg < Sk;
            const float* ksrc = Km + (((size_t)b * Sk + kg) * NH + h) * (size_t)HD + dq;
            const float* vsrc = Vm + (((size_t)b * Sk + kg) * NH + h) * (size_t)HD + dq;
            float4 z = {0.f, 0.f, 0.f, 0.f};
            #pragma unroll
            for (int i = 0; i < 4; i++) {
                pk[i] = ok ? *(const float4*)(ksrc + i * 4) : z;
                pv[i] = ok ? *(const float4*)(vsrc + i * 4) : z;
            }
        }

        float s[4][4];
        #pragma unroll
        for (int qi = 0; qi < 4; qi++)
            #pragma unroll
            for (int ki = 0; ki < 4; ki++) s[qi][ki] = 0.f;

        #pragma unroll
        for (int d0 = 0; d0 < HD; d0 += 4) {
            float4 q4[4], k4[4];
            #pragma unroll
            for (int qi = 0; qi < 4; qi++)
                q4[qi] = *(const float4*)&Qs[(qg * 4 + qi) * APAD + d0];
            #pragma unroll
            for (int ki = 0; ki < 4; ki++)
                k4[ki] = *(const float4*)&Ks[(j + 16 * ki) * APAD + d0];
            #pragma unroll
            for (int qi = 0; qi < 4; qi++)
                #pragma unroll
                for (int ki = 0; ki < 4; ki++) {
                    s[qi][ki] += q4[qi].x * k4[ki].x + q4[qi].y * k4[ki].y
                               + q4[qi].z * k4[ki].z + q4[qi].w * k4[ki].w;
                }
        }

        #pragma unroll
        for (int qi = 0; qi < 4; qi++) {
            int qgl = qt * ATQ + qg * 4 + qi;
            int kvalid = causal ? min(qgl + 1, Sk) : Sk;
            #pragma unroll
            for (int ki = 0; ki < 4; ki++) {
                int kg = kt * ATK + j + 16 * ki;
                s[qi][ki] = (kg < kvalid) ? s[qi][ki] * 0.125f : -1e30f;
            }
            float tm = fmaxf(fmaxf(s[qi][0], s[qi][1]), fmaxf(s[qi][2], s[qi][3]));
            #pragma unroll
            for (int off = 1; off < 16; off <<= 1)
                tm = fmaxf(tm, __shfl_xor_sync(0xffffffffu, tm, off));
            float mn = fmaxf(m_i[qi], tm);
            float scale = __expf(m_i[qi] - mn);
            float ps = 0.f;
            #pragma unroll
            for (int ki = 0; ki < 4; ki++) {
                float p = __expf(s[qi][ki] - mn);
                s[qi][ki] = p;
                ps += p;
            }
            #pragma unroll
            for (int off = 1; off < 16; off <<= 1)
                ps += __shfl_xor_sync(0xffffffffu, ps, off);
            l_i[qi] = l_i[qi] * scale + ps;
            m_i[qi] = mn;
            #pragma unroll
            for (int di = 0; di < 4; di++) acc[qi][di] *= scale;
        }

        #pragma unroll
        for (int ki = 0; ki < 4; ki++)
            #pragma unroll
            for (int qi = 0; qi < 4; qi++)
                Ss[(j + 16 * ki) * APAD + qg * 4 + qi] = s[qi][ki];
        __syncthreads();

        #pragma unroll 8
        for (int k = 0; k < ATK; k++) {
            float4 p4 = *(const float4*)&Ss[k * APAD + qg * 4];
            float4 v4 = *(const float4*)&Vs[k * APAD + j * 4];
            acc[0][0] += p4.x * v4.x; acc[0][1] += p4.x * v4.y;
            acc[0][2] += p4.x * v4.z; acc[0][3] += p4.x * v4.w;
            acc[1][0] += p4.y * v4.x; acc[1][1] += p4.y * v4.y;
            acc[1][2] += p4.y * v4.z; acc[1][3] += p4.y * v4.w;
            acc[2][0] += p4.z * v4.x; acc[2][1] += p4.z * v4.y;
            acc[2][2] += p4.z * v4.z; acc[2][3] += p4.z * v4.w;
            acc[3][0] += p4.w * v4.x; acc[3][1] += p4.w * v4.y;
            acc[3][2] += p4.w * v4.z; acc[3][3] += p4.w * v4.w;
        }
        __syncthreads();
    }

    int dd = j * 4;
    #pragma unroll
    for (int qi = 0; qi < 4; qi++) {
        int qgl = qt * ATQ + qg * 4 + qi;
        if (qgl < Sq) {
            float inv = 1.0f / l_i[qi];
            float4 o;
            o.x = acc[qi][0] * inv; o.y = acc[qi][1] * inv;
            o.z = acc[qi][2] * inv; o.w = acc[qi][3] * inv;
            *(float4*)&O[(((size_t)b * Sq + qgl) * NH + h) * (size_t)HD + dd] = o;
        }
    }
}

// ---------------- host orchestration ----------------
extern "C" void kernel_launch(void* const* d_in, const int* in_sizes, int n_in,
                              void* d_out, int out_size) {
    const float* tgt      = (const float*)d_in[0];
    const float* memory   = (const float*)d_in[1];
    const float* sa_in_w  = (const float*)d_in[2];
    const float* sa_in_b  = (const float*)d_in[3];
    const float* sa_out_w = (const float*)d_in[4];
    const float* sa_out_b = (const float*)d_in[5];
    const float* ca_in_w  = (const float*)d_in[6];
    const float* ca_in_b  = (const float*)d_in[7];
    const float* ca_out_w = (const float*)d_in[8];
    const float* ca_out_b = (const float*)d_in[9];
    const float* ff1_w    = (const float*)d_in[10];
    const float* ff1_b    = (const float*)d_in[11];
    const float* ff2_w    = (const float*)d_in[12];
    const float* ff2_b    = (const float*)d_in[13];
    const float* ln1_g    = (const float*)d_in[14];
    const float* ln1_b    = (const float*)d_in[15];
    const float* ln2_g    = (const float*)d_in[16];
    const float* ln2_b    = (const float*)d_in[17];
    const float* ln3_g    = (const float*)d_in[18];
    const float* ln3_b    = (const float*)d_in[19];
    float* out = (float*)d_out;

    float *p_h, *p_roped, *p_q, *p_k, *p_v, *p_attn, *p_x, *p_ffh;
    cudaGetSymbolAddress((void**)&p_h,     g_h);
    cudaGetSymbolAddress((void**)&p_roped, g_roped);
    cudaGetSymbolAddress((void**)&p_q,     g_q);
    cudaGetSymbolAddress((void**)&p_k,     g_k);
    cudaGetSymbolAddress((void**)&p_v,     g_v);
    cudaGetSymbolAddress((void**)&p_attn,  g_attn);
    cudaGetSymbolAddress((void**)&p_x,     g_x);
    cudaGetSymbolAddress((void**)&p_ffh,   g_ffh);

    static int smem_set = 0;
    int attn_smem = 4 * ATQ * APAD * sizeof(float);
    if (!smem_set) {
        cudaFuncSetAttribute(attn2_kernel, cudaFuncAttributeMaxDynamicSharedMemorySize, attn_smem);
        cudaFuncSetAttribute(sgemm_tf32, cudaFuncAttributeMaxDynamicSharedMemorySize, GSMEM);
        smem_set = 1;
    }

    dim3 gemm_nt_d(DMODEL / 128, NT / 128);
    dim3 gemm_mt_d(DMODEL / 128, MTOK / 128);
    dim3 gemm_ff1(DFF / 128, NT / 128);
    int rope_blocks = (NT * (DMODEL / 2) + 255) / 256;
    int qtiles = (SQ + ATQ - 1) / ATQ;

    // ---- self-attention block ----
    ln_kernel<<<NT, 256>>>(tgt, ln1_g, ln1_b, p_h);
    rope_kernel<<<rope_blocks, 256>>>(p_h, p_roped);
    sgemm_tf32<<<gemm_nt_d, 256, GSMEM>>>(p_roped, sa_in_w,                           sa_in_b,            nullptr, p_q, NT, DMODEL, DMODEL, 0);
    sgemm_tf32<<<gemm_nt_d, 256, GSMEM>>>(p_roped, sa_in_w + (size_t)DMODEL*DMODEL,   sa_in_b + DMODEL,   nullptr, p_k, NT, DMODEL, DMODEL, 0);
    sgemm_tf32<<<gemm_nt_d, 256, GSMEM>>>(p_h,     sa_in_w + (size_t)2*DMODEL*DMODEL, sa_in_b + 2*DMODEL, nullptr, p_v, NT, DMODEL, DMODEL, 0);
    attn2_kernel<<<dim3(qtiles, NH, BB), 256, attn_smem>>>(p_q, p_k, p_v, p_attn, SQ, SQ, 1);
    sgemm_tf32<<<gemm_nt_d, 256, GSMEM>>>(p_attn, sa_out_w, sa_out_b, tgt, p_x, NT, DMODEL, DMODEL, 2);

    // ---- cross-attention block ----
    ln_kernel<<<NT, 256>>>(p_x, ln2_g, ln2_b, p_h);
    sgemm_tf32<<<gemm_nt_d, 256, GSMEM>>>(p_h,    ca_in_w,                           ca_in_b,            nullptr, p_q, NT,   DMODEL, DMODEL, 0);
    sgemm_tf32<<<gemm_mt_d, 256, GSMEM>>>(memory, ca_in_w + (size_t)DMODEL*DMODEL,   ca_in_b + DMODEL,   nullptr, p_k, MTOK, DMODEL, DMODEL, 0);
    sgemm_tf32<<<gemm_mt_d, 256, GSMEM>>>(memory, ca_in_w + (size_t)2*DMODEL*DMODEL, ca_in_b + 2*DMODEL, nullptr, p_v, MTOK, DMODEL, DMODEL, 0);
    attn2_kernel<<<dim3(qtiles, NH, BB), 256, attn_smem>>>(p_q, p_k, p_v, p_attn, SQ, SMEMLEN, 0);
    sgemm_tf32<<<gemm_nt_d, 256, GSMEM>>>(p_attn, ca_out_w, ca_out_b, p_x, p_x, NT, DMODEL, DMODEL, 2);

    // ---- feed-forward block ----
    ln_kernel<<<NT, 256>>>(p_x, ln3_g, ln3_b, p_h);
    sgemm_tf32<<<gemm_ff1, 256, GSMEM>>>(p_h,   ff1_w, ff1_b, nullptr, p_ffh, NT, DFF, DMODEL, 1);
    sgemm_tf32<<<gemm_nt_d, 256, GSMEM>>>(p_ffh, ff2_w, ff2_b, p_x, out, NT, DMODEL, DFF, 2);
}